// round 2
// baseline (speedup 1.0000x reference)
#include <cuda_runtime.h>
#include <math.h>

#define BB 4
#define SS 4096
#define DD 1024
#define HH 64
#define NROW (BB*SS)

// Scratch for Q,K,V projections (allocation-free rule: __device__ globals).
__device__ float g_Q[NROW*HH];
__device__ float g_K[NROW*HH];
__device__ float g_V[NROW*HH];

// ---------------------------------------------------------------------------
// Kernel 1: QKV projection.  X:[NROW,1024] @ W:[1024,64] for q,k,v.
// Block = 64 rows x 64 cols, 256 threads, 4x4 register tiles per thread,
// K chunked by 32 with X staged transposed (d-major) in smem.
// Softmax scale (1/8) folded into Q at write time.
// ---------------------------------------------------------------------------
__global__ __launch_bounds__(256) void qkv_kernel(
    const float* __restrict__ X,
    const float* __restrict__ Wq,
    const float* __restrict__ Wk,
    const float* __restrict__ Wv)
{
    __shared__ float Xt[32*68];              // [dc][row], padded stride 68
    __shared__ float Wqs[32*64];             // [dc][h]
    __shared__ float Wks[32*64];
    __shared__ float Wvs[32*64];

    const int tid  = threadIdx.x;
    const int row0 = blockIdx.x * 64;
    const int tr   = tid >> 4;               // 0..15 -> rows tr*4..tr*4+3
    const int tc   = tid & 15;               // 0..15 -> cols tc*4..tc*4+3

    float aq[16], ak[16], av[16];
    #pragma unroll
    for (int i = 0; i < 16; ++i) { aq[i] = 0.f; ak[i] = 0.f; av[i] = 0.f; }

    for (int d0 = 0; d0 < DD; d0 += 32) {
        // Stage X tile transposed: Xt[dc][r]
        #pragma unroll
        for (int it = 0; it < 8; ++it) {
            int idx = tid + 256*it;          // 2048 elems
            int r   = idx >> 5;
            int dc  = idx & 31;
            Xt[dc*68 + r] = X[(row0 + r)*DD + d0 + dc];
        }
        // Stage W chunks (already d-major in gmem)
        #pragma unroll
        for (int it = 0; it < 8; ++it) {
            int idx = tid + 256*it;          // idx = dc*64 + h
            int dc  = idx >> 6;
            int h   = idx & 63;
            int g   = (d0 + dc)*HH + h;
            Wqs[idx] = Wq[g];
            Wks[idx] = Wk[g];
            Wvs[idx] = Wv[g];
        }
        __syncthreads();

        #pragma unroll
        for (int dc = 0; dc < 32; ++dc) {
            float4 x = *(const float4*)(Xt  + dc*68 + tr*4);
            float4 q = *(const float4*)(Wqs + dc*64 + tc*4);
            float4 k = *(const float4*)(Wks + dc*64 + tc*4);
            float4 v = *(const float4*)(Wvs + dc*64 + tc*4);
            float xs[4] = {x.x, x.y, x.z, x.w};
            float qs[4] = {q.x, q.y, q.z, q.w};
            float ks[4] = {k.x, k.y, k.z, k.w};
            float vs[4] = {v.x, v.y, v.z, v.w};
            #pragma unroll
            for (int i = 0; i < 4; ++i)
                #pragma unroll
                for (int j = 0; j < 4; ++j) {
                    aq[i*4+j] += xs[i]*qs[j];
                    ak[i*4+j] += xs[i]*ks[j];
                    av[i*4+j] += xs[i]*vs[j];
                }
        }
        __syncthreads();
    }

    #pragma unroll
    for (int i = 0; i < 4; ++i) {
        int row = row0 + tr*4 + i;
        float* qp = g_Q + row*HH + tc*4;
        float* kp = g_K + row*HH + tc*4;
        float* vp = g_V + row*HH + tc*4;
        float4 wq = make_float4(aq[i*4+0]*0.125f, aq[i*4+1]*0.125f,
                                aq[i*4+2]*0.125f, aq[i*4+3]*0.125f);
        float4 wk = make_float4(ak[i*4+0], ak[i*4+1], ak[i*4+2], ak[i*4+3]);
        float4 wv = make_float4(av[i*4+0], av[i*4+1], av[i*4+2], av[i*4+3]);
        *(float4*)qp = wq;
        *(float4*)kp = wk;
        *(float4*)vp = wv;
    }
}

// ---------------------------------------------------------------------------
// Kernel 2: causal flash attention, fp32.
// One CTA per (batch, 64-query tile).  256 threads.
// Qt/Kt stored d-major (transposed), P stored k-major -> both matmul phases
// are 2x LDS.128 + 16 FFMA per reduction step per thread.
// ---------------------------------------------------------------------------
struct AttnSmem {
    float Qt[64*68];   // [d][q], padded
    float Kt[64*68];   // [d][k], padded
    float Vs[64*64];   // [k][h]
    float Pt[64*68];   // [k][q], padded
    float m_s[64];
    float l_s[64];
    float a_s[64];
};

extern __shared__ char smem_raw[];

__global__ __launch_bounds__(256) void attn_kernel(float* __restrict__ out)
{
    AttnSmem& sm = *reinterpret_cast<AttnSmem*>(smem_raw);
    const int tid = threadIdx.x;
    const int qi  = 63 - (int)blockIdx.x;    // longest blocks first
    const int b   = blockIdx.y;
    const int q0  = qi * 64;
    const int tg  = tid >> 4;                // 0..15 : query group (rows tg*4..+3)
    const int tl  = tid & 15;                // 0..15 : key/head group (cols tl*4..+3)

    // Load Q tile transposed
    const float* Qg = g_Q + (size_t)(b*SS + q0)*HH;
    #pragma unroll
    for (int it = 0; it < 16; ++it) {
        int idx = tid + 256*it;              // idx = q*64 + d
        int q   = idx >> 6;
        int d   = idx & 63;
        sm.Qt[d*68 + q] = Qg[idx];
    }
    if (tid < 64) { sm.m_s[tid] = -INFINITY; sm.l_s[tid] = 0.f; }

    float o[16];
    #pragma unroll
    for (int i = 0; i < 16; ++i) o[i] = 0.f;
    __syncthreads();

    for (int kt = 0; kt <= qi; ++kt) {
        const float* Kg = g_K + (size_t)(b*SS + kt*64)*HH;
        const float* Vg = g_V + (size_t)(b*SS + kt*64)*HH;
        #pragma unroll
        for (int it = 0; it < 16; ++it) {
            int idx = tid + 256*it;          // idx = k*64 + d
            int k   = idx >> 6;
            int d   = idx & 63;
            sm.Kt[d*68 + k] = Kg[idx];
            sm.Vs[idx]      = Vg[idx];
        }
        __syncthreads();

        // --- scores: S[q][k] = Q . K  (scale already folded into Q) ---
        float s[16];
        #pragma unroll
        for (int i = 0; i < 16; ++i) s[i] = 0.f;
        #pragma unroll 8
        for (int d = 0; d < 64; ++d) {
            float4 qv = *(const float4*)(sm.Qt + d*68 + tg*4);
            float4 kv = *(const float4*)(sm.Kt + d*68 + tl*4);
            s[ 0] += qv.x*kv.x; s[ 1] += qv.x*kv.y; s[ 2] += qv.x*kv.z; s[ 3] += qv.x*kv.w;
            s[ 4] += qv.y*kv.x; s[ 5] += qv.y*kv.y; s[ 6] += qv.y*kv.z; s[ 7] += qv.y*kv.w;
            s[ 8] += qv.z*kv.x; s[ 9] += qv.z*kv.y; s[10] += qv.z*kv.z; s[11] += qv.z*kv.w;
            s[12] += qv.w*kv.x; s[13] += qv.w*kv.y; s[14] += qv.w*kv.z; s[15] += qv.w*kv.w;
        }
        if (kt == qi) {
            // diagonal tile: key_local > query_local -> mask
            #pragma unroll
            for (int i = 0; i < 4; ++i)
                #pragma unroll
                for (int j = 0; j < 4; ++j)
                    if (tl*4 + j > tg*4 + i) s[i*4+j] = -INFINITY;
        }

        // --- online softmax per row (16-lane groups share a row group) ---
        #pragma unroll
        for (int i = 0; i < 4; ++i) {
            float rmax = fmaxf(fmaxf(s[i*4+0], s[i*4+1]), fmaxf(s[i*4+2], s[i*4+3]));
            #pragma unroll
            for (int x = 1; x < 16; x <<= 1)
                rmax = fmaxf(rmax, __shfl_xor_sync(0xffffffffu, rmax, x));
            const int q = tg*4 + i;
            float m_old = sm.m_s[q];
            float m_new = fmaxf(m_old, rmax);
            float alpha = __expf(m_old - m_new);
            float p0 = __expf(s[i*4+0] - m_new);
            float p1 = __expf(s[i*4+1] - m_new);
            float p2 = __expf(s[i*4+2] - m_new);
            float p3 = __expf(s[i*4+3] - m_new);
            float rs = (p0 + p1) + (p2 + p3);
            #pragma unroll
            for (int x = 1; x < 16; x <<= 1)
                rs += __shfl_xor_sync(0xffffffffu, rs, x);
            if (tl == 0) {
                sm.m_s[q] = m_new;
                sm.a_s[q] = alpha;
                sm.l_s[q] = sm.l_s[q]*alpha + rs;
            }
            sm.Pt[(tl*4+0)*68 + q] = p0;
            sm.Pt[(tl*4+1)*68 + q] = p1;
            sm.Pt[(tl*4+2)*68 + q] = p2;
            sm.Pt[(tl*4+3)*68 + q] = p3;
        }
        __syncthreads();

        // --- PV: O[q][h] = O*alpha + P @ V ---
        float al[4];
        #pragma unroll
        for (int i = 0; i < 4; ++i) al[i] = sm.a_s[tg*4 + i];
        #pragma unroll
        for (int i = 0; i < 4; ++i)
            #pragma unroll
            for (int j = 0; j < 4; ++j) o[i*4+j] *= al[i];

        #pragma unroll 8
        for (int k = 0; k < 64; ++k) {
            float4 pv = *(const float4*)(sm.Pt + k*68 + tg*4);
            float4 vv = *(const float4*)(sm.Vs + k*64 + tl*4);
            o[ 0] += pv.x*vv.x; o[ 1] += pv.x*vv.y; o[ 2] += pv.x*vv.z; o[ 3] += pv.x*vv.w;
            o[ 4] += pv.y*vv.x; o[ 5] += pv.y*vv.y; o[ 6] += pv.y*vv.z; o[ 7] += pv.y*vv.w;
            o[ 8] += pv.z*vv.x; o[ 9] += pv.z*vv.y; o[10] += pv.z*vv.z; o[11] += pv.z*vv.w;
            o[12] += pv.w*vv.x; o[13] += pv.w*vv.y; o[14] += pv.w*vv.z; o[15] += pv.w*vv.w;
        }
        __syncthreads();
    }

    // normalize + write
    float* Og = out + (size_t)(b*SS + q0)*HH;
    #pragma unroll
    for (int i = 0; i < 4; ++i) {
        float linv = 1.f / sm.l_s[tg*4 + i];
        float4 r = make_float4(o[i*4+0]*linv, o[i*4+1]*linv,
                               o[i*4+2]*linv, o[i*4+3]*linv);
        *(float4*)(Og + (tg*4 + i)*HH + tl*4) = r;
    }
}

// ---------------------------------------------------------------------------
extern "C" void kernel_launch(void* const* d_in, const int* in_sizes, int n_in,
                              void* d_out, int out_size)
{
    const float* X  = (const float*)d_in[0];
    const float* Wq = (const float*)d_in[1];
    const float* Wk = (const float*)d_in[2];
    const float* Wv = (const float*)d_in[3];
    float* out = (float*)d_out;

    qkv_kernel<<<NROW/64, 256>>>(X, Wq, Wk, Wv);

    const int smem_bytes = (int)sizeof(AttnSmem);   // ~69 KB
    cudaFuncSetAttribute(attn_kernel,
                         cudaFuncAttributeMaxDynamicSharedMemorySize, smem_bytes);
    attn_kernel<<<dim3(SS/64, BB), 256, smem_bytes>>>(out);
}

// round 3
// speedup vs baseline: 1.6191x; 1.6191x over previous
#include <cuda_runtime.h>
#include <math.h>

#define BB 4
#define SS 4096
#define DD 1024
#define HH 64
#define NROW (BB*SS)

// Scratch for Q,K,V projections (allocation-free rule: __device__ globals).
__device__ float g_Q[NROW*HH];
__device__ float g_K[NROW*HH];
__device__ float g_V[NROW*HH];

// ---------------------------------------------------------------------------
// Kernel 1: QKV projection.  X:[NROW,1024] @ W:[1024,64] for q,k,v.
// Block = 64 rows x 64 cols, 256 threads, 4x4 register tiles per thread,
// K chunked by 32 with X staged transposed (d-major) in smem.
// Softmax scale (1/8) folded into Q at write time.
// ---------------------------------------------------------------------------
__global__ __launch_bounds__(256) void qkv_kernel(
    const float* __restrict__ X,
    const float* __restrict__ Wq,
    const float* __restrict__ Wk,
    const float* __restrict__ Wv)
{
    __shared__ float Xt[32*68];              // [dc][row], padded stride 68
    __shared__ float Wqs[32*64];             // [dc][h]
    __shared__ float Wks[32*64];
    __shared__ float Wvs[32*64];

    const int tid  = threadIdx.x;
    const int row0 = blockIdx.x * 64;
    const int tr   = tid >> 4;               // 0..15 -> rows tr*4..tr*4+3
    const int tc   = tid & 15;               // 0..15 -> cols tc*4..tc*4+3

    float aq[16], ak[16], av[16];
    #pragma unroll
    for (int i = 0; i < 16; ++i) { aq[i] = 0.f; ak[i] = 0.f; av[i] = 0.f; }

    for (int d0 = 0; d0 < DD; d0 += 32) {
        // Stage X tile transposed: Xt[dc][r]
        #pragma unroll
        for (int it = 0; it < 8; ++it) {
            int idx = tid + 256*it;          // 2048 elems
            int r   = idx >> 5;
            int dc  = idx & 31;
            Xt[dc*68 + r] = X[(row0 + r)*DD + d0 + dc];
        }
        // Stage W chunks (already d-major in gmem)
        #pragma unroll
        for (int it = 0; it < 8; ++it) {
            int idx = tid + 256*it;          // idx = dc*64 + h
            int dc  = idx >> 6;
            int h   = idx & 63;
            int g   = (d0 + dc)*HH + h;
            Wqs[idx] = Wq[g];
            Wks[idx] = Wk[g];
            Wvs[idx] = Wv[g];
        }
        __syncthreads();

        #pragma unroll
        for (int dc = 0; dc < 32; ++dc) {
            float4 x = *(const float4*)(Xt  + dc*68 + tr*4);
            float4 q = *(const float4*)(Wqs + dc*64 + tc*4);
            float4 k = *(const float4*)(Wks + dc*64 + tc*4);
            float4 v = *(const float4*)(Wvs + dc*64 + tc*4);
            float xs[4] = {x.x, x.y, x.z, x.w};
            float qs[4] = {q.x, q.y, q.z, q.w};
            float ks[4] = {k.x, k.y, k.z, k.w};
            float vs[4] = {v.x, v.y, v.z, v.w};
            #pragma unroll
            for (int i = 0; i < 4; ++i)
                #pragma unroll
                for (int j = 0; j < 4; ++j) {
                    aq[i*4+j] += xs[i]*qs[j];
                    ak[i*4+j] += xs[i]*ks[j];
                    av[i*4+j] += xs[i]*vs[j];
                }
        }
        __syncthreads();
    }

    #pragma unroll
    for (int i = 0; i < 4; ++i) {
        int row = row0 + tr*4 + i;
        float* qp = g_Q + row*HH + tc*4;
        float* kp = g_K + row*HH + tc*4;
        float* vp = g_V + row*HH + tc*4;
        float4 wq = make_float4(aq[i*4+0]*0.125f, aq[i*4+1]*0.125f,
                                aq[i*4+2]*0.125f, aq[i*4+3]*0.125f);
        float4 wk = make_float4(ak[i*4+0], ak[i*4+1], ak[i*4+2], ak[i*4+3]);
        float4 wv = make_float4(av[i*4+0], av[i*4+1], av[i*4+2], av[i*4+3]);
        *(float4*)qp = wq;
        *(float4*)kp = wk;
        *(float4*)vp = wv;
    }
}

// ---------------------------------------------------------------------------
// Kernel 2: causal flash attention, fp32.
// One CTA per (batch, 64-query tile).  256 threads.
// Qt/Kt stored d-major (transposed), P stored k-major -> both matmul phases
// are 2x LDS.128 + 16 FFMA per reduction step per thread.
// ---------------------------------------------------------------------------
struct AttnSmem {
    float Qt[64*68];   // [d][q], padded
    float Kt[64*68];   // [d][k], padded
    float Vs[64*64];   // [k][h]
    float Pt[64*68];   // [k][q], padded
    float m_s[64];
    float l_s[64];
    float a_s[64];
};

extern __shared__ char smem_raw[];

__global__ __launch_bounds__(256) void attn_kernel(float* __restrict__ out)
{
    AttnSmem& sm = *reinterpret_cast<AttnSmem*>(smem_raw);
    const int tid = threadIdx.x;
    const int qi  = 63 - (int)blockIdx.x;    // longest blocks first
    const int b   = blockIdx.y;
    const int q0  = qi * 64;
    const int tg  = tid >> 4;                // 0..15 : query group (rows tg*4..+3)
    const int tl  = tid & 15;                // 0..15 : key/head group (cols tl*4..+3)

    // Load Q tile transposed
    const float* Qg = g_Q + (size_t)(b*SS + q0)*HH;
    #pragma unroll
    for (int it = 0; it < 16; ++it) {
        int idx = tid + 256*it;              // idx = q*64 + d
        int q   = idx >> 6;
        int d   = idx & 63;
        sm.Qt[d*68 + q] = Qg[idx];
    }
    if (tid < 64) { sm.m_s[tid] = -INFINITY; sm.l_s[tid] = 0.f; }

    float o[16];
    #pragma unroll
    for (int i = 0; i < 16; ++i) o[i] = 0.f;
    __syncthreads();

    for (int kt = 0; kt <= qi; ++kt) {
        const float* Kg = g_K + (size_t)(b*SS + kt*64)*HH;
        const float* Vg = g_V + (size_t)(b*SS + kt*64)*HH;
        #pragma unroll
        for (int it = 0; it < 16; ++it) {
            int idx = tid + 256*it;          // idx = k*64 + d
            int k   = idx >> 6;
            int d   = idx & 63;
            sm.Kt[d*68 + k] = Kg[idx];
            sm.Vs[idx]      = Vg[idx];
        }
        __syncthreads();

        // --- scores: S[q][k] = Q . K  (scale already folded into Q) ---
        float s[16];
        #pragma unroll
        for (int i = 0; i < 16; ++i) s[i] = 0.f;
        #pragma unroll 8
        for (int d = 0; d < 64; ++d) {
            float4 qv = *(const float4*)(sm.Qt + d*68 + tg*4);
            float4 kv = *(const float4*)(sm.Kt + d*68 + tl*4);
            s[ 0] += qv.x*kv.x; s[ 1] += qv.x*kv.y; s[ 2] += qv.x*kv.z; s[ 3] += qv.x*kv.w;
            s[ 4] += qv.y*kv.x; s[ 5] += qv.y*kv.y; s[ 6] += qv.y*kv.z; s[ 7] += qv.y*kv.w;
            s[ 8] += qv.z*kv.x; s[ 9] += qv.z*kv.y; s[10] += qv.z*kv.z; s[11] += qv.z*kv.w;
            s[12] += qv.w*kv.x; s[13] += qv.w*kv.y; s[14] += qv.w*kv.z; s[15] += qv.w*kv.w;
        }
        if (kt == qi) {
            // diagonal tile: key_local > query_local -> mask
            #pragma unroll
            for (int i = 0; i < 4; ++i)
                #pragma unroll
                for (int j = 0; j < 4; ++j)
                    if (tl*4 + j > tg*4 + i) s[i*4+j] = -INFINITY;
        }

        // --- online softmax per row (16-lane groups share a row group) ---
        #pragma unroll
        for (int i = 0; i < 4; ++i) {
            float rmax = fmaxf(fmaxf(s[i*4+0], s[i*4+1]), fmaxf(s[i*4+2], s[i*4+3]));
            #pragma unroll
            for (int x = 1; x < 16; x <<= 1)
                rmax = fmaxf(rmax, __shfl_xor_sync(0xffffffffu, rmax, x));
            const int q = tg*4 + i;
            float m_old = sm.m_s[q];
            float m_new = fmaxf(m_old, rmax);
            float alpha = __expf(m_old - m_new);
            float p0 = __expf(s[i*4+0] - m_new);
            float p1 = __expf(s[i*4+1] - m_new);
            float p2 = __expf(s[i*4+2] - m_new);
            float p3 = __expf(s[i*4+3] - m_new);
            float rs = (p0 + p1) + (p2 + p3);
            #pragma unroll
            for (int x = 1; x < 16; x <<= 1)
                rs += __shfl_xor_sync(0xffffffffu, rs, x);
            if (tl == 0) {
                sm.m_s[q] = m_new;
                sm.a_s[q] = alpha;
                sm.l_s[q] = sm.l_s[q]*alpha + rs;
            }
            sm.Pt[(tl*4+0)*68 + q] = p0;
            sm.Pt[(tl*4+1)*68 + q] = p1;
            sm.Pt[(tl*4+2)*68 + q] = p2;
            sm.Pt[(tl*4+3)*68 + q] = p3;
        }
        __syncthreads();

        // --- PV: O[q][h] = O*alpha + P @ V ---
        float al[4];
        #pragma unroll
        for (int i = 0; i < 4; ++i) al[i] = sm.a_s[tg*4 + i];
        #pragma unroll
        for (int i = 0; i < 4; ++i)
            #pragma unroll
            for (int j = 0; j < 4; ++j) o[i*4+j] *= al[i];

        #pragma unroll 8
        for (int k = 0; k < 64; ++k) {
            float4 pv = *(const float4*)(sm.Pt + k*68 + tg*4);
            float4 vv = *(const float4*)(sm.Vs + k*64 + tl*4);
            o[ 0] += pv.x*vv.x; o[ 1] += pv.x*vv.y; o[ 2] += pv.x*vv.z; o[ 3] += pv.x*vv.w;
            o[ 4] += pv.y*vv.x; o[ 5] += pv.y*vv.y; o[ 6] += pv.y*vv.z; o[ 7] += pv.y*vv.w;
            o[ 8] += pv.z*vv.x; o[ 9] += pv.z*vv.y; o[10] += pv.z*vv.z; o[11] += pv.z*vv.w;
            o[12] += pv.w*vv.x; o[13] += pv.w*vv.y; o[14] += pv.w*vv.z; o[15] += pv.w*vv.w;
        }
        __syncthreads();
    }

    // normalize + write
    float* Og = out + (size_t)(b*SS + q0)*HH;
    #pragma unroll
    for (int i = 0; i < 4; ++i) {
        float linv = 1.f / sm.l_s[tg*4 + i];
        float4 r = make_float4(o[i*4+0]*linv, o[i*4+1]*linv,
                               o[i*4+2]*linv, o[i*4+3]*linv);
        *(float4*)(Og + (tg*4 + i)*HH + tl*4) = r;
    }
}

// ---------------------------------------------------------------------------
extern "C" void kernel_launch(void* const* d_in, const int* in_sizes, int n_in,
                              void* d_out, int out_size)
{
    const float* X  = (const float*)d_in[0];
    const float* Wq = (const float*)d_in[1];
    const float* Wk = (const float*)d_in[2];
    const float* Wv = (const float*)d_in[3];
    float* out = (float*)d_out;

    qkv_kernel<<<NROW/64, 256>>>(X, Wq, Wk, Wv);

    const int smem_bytes = (int)sizeof(AttnSmem);   // ~69 KB
    cudaFuncSetAttribute(attn_kernel,
                         cudaFuncAttributeMaxDynamicSharedMemorySize, smem_bytes);
    attn_kernel<<<dim3(SS/64, BB), 256, smem_bytes>>>(out);
}

// round 5
// speedup vs baseline: 4.9793x; 3.0754x over previous
#include <cuda_runtime.h>
#include <cuda_bf16.h>
#include <cstdint>
#include <math.h>

#define BB 4
#define SS 4096
#define DD 1024
#define HH 64
#define NROW (BB*SS)

// ---------------- scratch (__device__ globals; allocation-free rule) -------
__device__ uint32_t g_Qh[NROW*32], g_Ql[NROW*32];       // [row][d-pair] bf16x2
__device__ uint32_t g_Kh[NROW*32], g_Kl[NROW*32];       // [row][d-pair]
__device__ uint32_t g_Vth[BB*64*2048], g_Vtl[BB*64*2048]; // [b][h][seq-pair]
__device__ uint32_t g_Wth[192*512], g_Wtl[192*512];     // [n(=3*64)][d-pair]
__device__ float    g_O[2][NROW*64];                    // split-k partial O
__device__ float    g_L[2][NROW];                       // split-k partial rowsum

// ---------------- helpers --------------------------------------------------
__device__ __forceinline__ uint32_t smem_u32(const void* p){
    uint32_t a;
    asm("{ .reg .u64 t; cvta.to.shared.u64 t, %1; cvt.u32.u64 %0, t; }"
        : "=r"(a) : "l"(p));
    return a;
}

// mma.sync m16n8k16 row.col f32.bf16.bf16.f32  (works on plain compute_103)
__device__ __forceinline__ void mma16816(float* d, const uint32_t* a,
                                         const uint32_t* b){
    asm volatile(
        "mma.sync.aligned.m16n8k16.row.col.f32.bf16.bf16.f32 "
        "{%0,%1,%2,%3}, {%4,%5,%6,%7}, {%8,%9}, {%0,%1,%2,%3};"
        : "+f"(d[0]), "+f"(d[1]), "+f"(d[2]), "+f"(d[3])
        : "r"(a[0]), "r"(a[1]), "r"(a[2]), "r"(a[3]), "r"(b[0]), "r"(b[1]));
}
__device__ __forceinline__ void ldsm4(uint32_t* r, uint32_t addr){
    asm volatile("ldmatrix.sync.aligned.m8n8.x4.shared.b16 {%0,%1,%2,%3}, [%4];"
        : "=r"(r[0]), "=r"(r[1]), "=r"(r[2]), "=r"(r[3]) : "r"(addr));
}
__device__ __forceinline__ void ldsm2(uint32_t* r, uint32_t addr){
    asm volatile("ldmatrix.sync.aligned.m8n8.x2.shared.b16 {%0,%1}, [%2];"
        : "=r"(r[0]), "=r"(r[1]) : "r"(addr));
}

// split-bf16: (f0,f1) -> hi bf16x2 (f0 low half) + lo residual bf16x2
__device__ __forceinline__ uint32_t bfpack(float lo, float hi){
    uint32_t r;
    asm("cvt.rn.bf16x2.f32 %0, %1, %2;" : "=r"(r) : "f"(hi), "f"(lo));
    return r;
}
__device__ __forceinline__ void split2(float f0, float f1,
                                       uint32_t& hv, uint32_t& lv){
    hv = bfpack(f0, f1);
    float h0 = __uint_as_float(hv << 16);
    float h1 = __uint_as_float(hv & 0xffff0000u);
    lv = bfpack(f0 - h0, f1 - h1);
}

// swizzled byte offset inside a [row][128B] tile (conflict-free ldmatrix)
__device__ __forceinline__ uint32_t swz(int r, int bytecol){
    return (uint32_t)(r*128 + (bytecol ^ ((r & 7) << 4)));
}

// ---------------------------------------------------------------------------
// Kernel 0: transpose+split W -> g_Wth/g_Wtl [n][d-pair], n = reg*64+h
// ---------------------------------------------------------------------------
__global__ __launch_bounds__(256) void prep_w(
    const float* __restrict__ Wq, const float* __restrict__ Wk,
    const float* __restrict__ Wv)
{
    int idx = blockIdx.x*256 + threadIdx.x;      // 0..98303
    if (idx >= 192*512) return;
    int n = idx >> 9, dp = idx & 511;
    const float* W = (n < 64) ? Wq : (n < 128) ? Wk : Wv;
    int h = n & 63, d = dp*2;
    uint32_t hv, lv;
    split2(W[d*64 + h], W[(d+1)*64 + h], hv, lv);
    g_Wth[idx] = hv;  g_Wtl[idx] = lv;
}

// ---------------------------------------------------------------------------
// Kernel 1: QKV via mma.sync.  128 CTAs x 256 thr.  CTA: 128 rows x 192 cols.
// K chunked by 64; X split to bf16 hi/lo inline.
// smem: XH@0 XL@16384 (16KB ea), WH@32768 WL@57344 (24KB ea) = 80KB dynamic.
// ---------------------------------------------------------------------------
extern __shared__ char dsm[];

__global__ __launch_bounds__(256) void qkv_mma(const float* __restrict__ X)
{
    char* sm = dsm;
    uint32_t sb  = smem_u32(sm);
    const uint32_t xh = sb, xl = sb + 16384, wh = sb + 32768, wl = sb + 57344;

    const int tid = threadIdx.x, w = tid >> 5, lane = tid & 31;
    const int gid = lane >> 2, tig = lane & 3;
    const int row0 = blockIdx.x * 128;
    const int mrow = w * 16;

    // ldmatrix per-lane address components
    const int aR   = mrow + (lane & 7) + ((lane >> 3) & 1) * 8;  // A row
    const uint32_t aOff = (uint32_t)aR * 128;
    const int aSeg = (lane >> 4) ? 16 : 0;
    const uint32_t aX = (uint32_t)((lane & 7) << 4);
    const uint32_t bOff = (uint32_t)((lane & 7) * 128);
    const int bSeg = (lane & 8) ? 16 : 0;
    const uint32_t bX = (uint32_t)((lane & 7) << 4);

    float acc[24][4];
    #pragma unroll
    for (int nt = 0; nt < 24; ++nt)
        #pragma unroll
        for (int j = 0; j < 4; ++j) acc[nt][j] = 0.f;

    for (int kc = 0; kc < 16; ++kc) {
        const int d0 = kc * 64;
        // stage X chunk (split on the fly)
        #pragma unroll
        for (int i = 0; i < 16; ++i) {
            int idx = tid + 256*i;               // 4096 pairs
            int r = idx >> 5, cp = idx & 31;
            float2 x = *(const float2*)(X + (size_t)(row0 + r)*DD + d0 + 2*cp);
            uint32_t hv, lv; split2(x.x, x.y, hv, lv);
            uint32_t off = swz(r, cp*4);
            *(uint32_t*)(sm + off)         = hv;
            *(uint32_t*)(sm + 16384 + off) = lv;
        }
        // stage W chunk (pre-split)
        #pragma unroll
        for (int i = 0; i < 24; ++i) {
            int idx = tid + 256*i;               // 6144 words
            int r = idx >> 5, cp = idx & 31;
            uint32_t src = (uint32_t)r*512 + (uint32_t)(d0 >> 1) + cp;
            uint32_t off = swz(r, cp*4);
            *(uint32_t*)(sm + 32768 + off) = g_Wth[src];
            *(uint32_t*)(sm + 57344 + off) = g_Wtl[src];
        }
        __syncthreads();

        #pragma unroll
        for (int ks = 0; ks < 4; ++ks) {
            uint32_t ah[4], al[4];
            uint32_t aoffs = aOff + (uint32_t)((ks*32 + aSeg) ^ aX);
            ldsm4(ah, xh + aoffs);
            ldsm4(al, xl + aoffs);
            uint32_t kk = bOff + (uint32_t)((ks*32 + bSeg) ^ bX);
            #pragma unroll
            for (int nt = 0; nt < 24; ++nt) {
                uint32_t bhv[2], blv[2];
                ldsm2(bhv, wh + nt*1024 + kk);
                ldsm2(blv, wl + nt*1024 + kk);
                mma16816(acc[nt], ah, bhv);
                mma16816(acc[nt], ah, blv);
                mma16816(acc[nt], al, bhv);
            }
        }
        __syncthreads();
    }

    // epilogue: Q (x0.125) and K row-major split-bf16
    const int r0g = row0 + mrow + gid, r1g = r0g + 8;
    #pragma unroll
    for (int nt = 0; nt < 8; ++nt) {
        uint32_t hv, lv;
        split2(acc[nt][0]*0.125f, acc[nt][1]*0.125f, hv, lv);
        g_Qh[r0g*32 + nt*4 + tig] = hv;  g_Ql[r0g*32 + nt*4 + tig] = lv;
        split2(acc[nt][2]*0.125f, acc[nt][3]*0.125f, hv, lv);
        g_Qh[r1g*32 + nt*4 + tig] = hv;  g_Ql[r1g*32 + nt*4 + tig] = lv;
    }
    #pragma unroll
    for (int nt = 8; nt < 16; ++nt) {
        uint32_t hv, lv;
        int c = (nt - 8)*4 + tig;
        split2(acc[nt][0], acc[nt][1], hv, lv);
        g_Kh[r0g*32 + c] = hv;  g_Kl[r0g*32 + c] = lv;
        split2(acc[nt][2], acc[nt][3], hv, lv);
        g_Kh[r1g*32 + c] = hv;  g_Kl[r1g*32 + c] = lv;
    }
    // V: transpose through smem (reuse X area), then split-write [b][h][sp]
    __syncthreads();
    float* Vt = (float*)sm;                      // [h][128 seq local]
    #pragma unroll
    for (int nt = 16; nt < 24; ++nt) {
        int h0 = (nt - 16)*8 + tig*2;
        Vt[h0*128 + mrow + gid]           = acc[nt][0];
        Vt[(h0+1)*128 + mrow + gid]       = acc[nt][1];
        Vt[h0*128 + mrow + gid + 8]       = acc[nt][2];
        Vt[(h0+1)*128 + mrow + gid + 8]   = acc[nt][3];
    }
    __syncthreads();
    const int bb = row0 >> 12, sloc = row0 & 4095;
    #pragma unroll
    for (int i = 0; i < 16; ++i) {
        int idx = tid + 256*i;                   // 4096: h(64) x sp(64)
        int h = idx >> 6, sp = idx & 63;
        uint32_t hv, lv;
        split2(Vt[h*128 + 2*sp], Vt[h*128 + 2*sp + 1], hv, lv);
        size_t o = (size_t)(bb*64 + h)*2048 + (sloc >> 1) + sp;
        g_Vth[o] = hv;  g_Vtl[o] = lv;
    }
}

// ---------------------------------------------------------------------------
// Kernel 2: causal attention via mma.sync, split-bf16, no-max softmax.
// grid (64, 4): x -> (qq = 31 - x/2 longest-first, split s = x&1), y = batch.
// Q fragments in registers; P converted C-frag -> A-frag in registers.
// ---------------------------------------------------------------------------
__global__ __launch_bounds__(256) void attn_mma()
{
    __shared__ __align__(128) uint32_t sKh[2048], sKl[2048];
    __shared__ __align__(128) uint32_t sVh[2048], sVl[2048];
    const uint32_t kh = smem_u32(sKh), kl = smem_u32(sKl);
    const uint32_t vh = smem_u32(sVh), vl = smem_u32(sVl);

    const int tid = threadIdx.x, w = tid >> 5, lane = tid & 31;
    const int gid = lane >> 2, tig = lane & 3;
    const int bx = blockIdx.x;
    const int qq = 31 - (bx >> 1);
    const int s  = bx & 1;
    const int b  = blockIdx.y;
    const int q0 = qq * 128;

    const uint32_t bOff = (uint32_t)((lane & 7) * 128);
    const int bSeg = (lane & 8) ? 16 : 0;
    const uint32_t bX = (uint32_t)((lane & 7) << 4);

    // Q fragments from gmem (once)
    const int r0g = b*SS + q0 + w*16 + gid, r1g = r0g + 8;
    uint32_t qfh[4][4], qfl[4][4];
    #pragma unroll
    for (int ks = 0; ks < 4; ++ks) {
        qfh[ks][0] = g_Qh[r0g*32 + ks*8 + tig];
        qfh[ks][1] = g_Qh[r1g*32 + ks*8 + tig];
        qfh[ks][2] = g_Qh[r0g*32 + ks*8 + 4 + tig];
        qfh[ks][3] = g_Qh[r1g*32 + ks*8 + 4 + tig];
        qfl[ks][0] = g_Ql[r0g*32 + ks*8 + tig];
        qfl[ks][1] = g_Ql[r1g*32 + ks*8 + tig];
        qfl[ks][2] = g_Ql[r0g*32 + ks*8 + 4 + tig];
        qfl[ks][3] = g_Ql[r1g*32 + ks*8 + 4 + tig];
    }

    float oc[8][4];
    #pragma unroll
    for (int nt = 0; nt < 8; ++nt)
        #pragma unroll
        for (int j = 0; j < 4; ++j) oc[nt][j] = 0.f;
    float ls0 = 0.f, ls1 = 0.f;

    const int qg0 = q0 + w*16 + gid, qg1 = qg0 + 8;
    const uint32_t* KH = g_Kh + (size_t)(b*SS)*32;
    const uint32_t* KL = g_Kl + (size_t)(b*SS)*32;
    const uint32_t* VH = g_Vth + (size_t)(b*64)*2048;
    const uint32_t* VL = g_Vtl + (size_t)(b*64)*2048;

    for (int t = 0; t <= qq; ++t) {
        const int kt = s + 2*t;
        const int k0 = kt * 64;

        // stage K and Vt tiles (swizzled)
        #pragma unroll
        for (int i = 0; i < 8; ++i) {
            int idx = tid + 256*i;               // 2048 words / array
            int r = idx >> 5, cp = idx & 31;
            uint32_t off = swz(r, cp*4) >> 2;
            sKh[off] = KH[(size_t)(k0 + r)*32 + cp];
            sKl[off] = KL[(size_t)(k0 + r)*32 + cp];
            sVh[off] = VH[(size_t)r*2048 + (k0 >> 1) + cp];
            sVl[off] = VL[(size_t)r*2048 + (k0 >> 1) + cp];
        }
        __syncthreads();

        // scores
        float sc[8][4];
        #pragma unroll
        for (int nt = 0; nt < 8; ++nt)
            #pragma unroll
            for (int j = 0; j < 4; ++j) sc[nt][j] = 0.f;
        #pragma unroll
        for (int ks = 0; ks < 4; ++ks) {
            uint32_t kk = bOff + (uint32_t)((ks*32 + bSeg) ^ bX);
            #pragma unroll
            for (int nt = 0; nt < 8; ++nt) {
                uint32_t bhv[2], blv[2];
                ldsm2(bhv, kh + nt*1024 + kk);
                ldsm2(blv, kl + nt*1024 + kk);
                mma16816(sc[nt], qfh[ks], bhv);
                mma16816(sc[nt], qfh[ks], blv);
                mma16816(sc[nt], qfl[ks], bhv);
            }
        }

        // mask + exp + split P into A-fragment layout (registers only)
        uint32_t ph[16], pl[16];
        #pragma unroll
        for (int nt = 0; nt < 8; ++nt) {
            int kg = k0 + nt*8 + tig*2;
            float p0 = (kg     <= qg0) ? __expf(sc[nt][0]) : 0.f;
            float p1 = (kg + 1 <= qg0) ? __expf(sc[nt][1]) : 0.f;
            float p2 = (kg     <= qg1) ? __expf(sc[nt][2]) : 0.f;
            float p3 = (kg + 1 <= qg1) ? __expf(sc[nt][3]) : 0.f;
            ls0 += p0 + p1;  ls1 += p2 + p3;
            split2(p0, p1, ph[nt*2],     pl[nt*2]);
            split2(p2, p3, ph[nt*2 + 1], pl[nt*2 + 1]);
        }

        // O += P . Vt^T
        #pragma unroll
        for (int kc = 0; kc < 4; ++kc) {
            uint32_t kk = bOff + (uint32_t)((kc*32 + bSeg) ^ bX);
            const uint32_t* ah = &ph[kc*4];
            const uint32_t* al = &pl[kc*4];
            #pragma unroll
            for (int nt = 0; nt < 8; ++nt) {
                uint32_t bhv[2], blv[2];
                ldsm2(bhv, vh + nt*1024 + kk);
                ldsm2(blv, vl + nt*1024 + kk);
                mma16816(oc[nt], ah, bhv);
                mma16816(oc[nt], ah, blv);
                mma16816(oc[nt], al, bhv);
            }
        }
        __syncthreads();
    }

    // write partial O
    float* Og = g_O[s];
    const size_t ob0 = (size_t)(b*SS + q0 + w*16 + gid)*64;
    #pragma unroll
    for (int nt = 0; nt < 8; ++nt) {
        *(float2*)&Og[ob0 + nt*8 + tig*2]          = make_float2(oc[nt][0], oc[nt][1]);
        *(float2*)&Og[ob0 + 8*64 + nt*8 + tig*2]   = make_float2(oc[nt][2], oc[nt][3]);
    }
    // partial row sums (reduce across quad)
    ls0 += __shfl_xor_sync(0xffffffffu, ls0, 1);
    ls0 += __shfl_xor_sync(0xffffffffu, ls0, 2);
    ls1 += __shfl_xor_sync(0xffffffffu, ls1, 1);
    ls1 += __shfl_xor_sync(0xffffffffu, ls1, 2);
    if (tig == 0) {
        g_L[s][b*SS + q0 + w*16 + gid]     = ls0;
        g_L[s][b*SS + q0 + w*16 + gid + 8] = ls1;
    }
}

// ---------------------------------------------------------------------------
// Kernel 3: combine split-k partials and normalize.
// ---------------------------------------------------------------------------
__global__ __launch_bounds__(256) void finalize(float* __restrict__ out)
{
    int idx = blockIdx.x*256 + threadIdx.x;
    float o = g_O[0][idx] + g_O[1][idx];
    float l = g_L[0][idx >> 6] + g_L[1][idx >> 6];
    out[idx] = o / l;
}

// ---------------------------------------------------------------------------
extern "C" void kernel_launch(void* const* d_in, const int* in_sizes, int n_in,
                              void* d_out, int out_size)
{
    const float* X  = (const float*)d_in[0];
    const float* Wq = (const float*)d_in[1];
    const float* Wk = (const float*)d_in[2];
    const float* Wv = (const float*)d_in[3];
    float* out = (float*)d_out;

    prep_w<<<384, 256>>>(Wq, Wk, Wv);

    const int qkv_smem = 81920;
    cudaFuncSetAttribute(qkv_mma,
                         cudaFuncAttributeMaxDynamicSharedMemorySize, qkv_smem);
    qkv_mma<<<128, 256, qkv_smem>>>(X);

    attn_mma<<<dim3(64, BB), 256>>>();

    finalize<<<(NROW*64)/256, 256>>>(out);
}

// round 7
// speedup vs baseline: 6.9893x; 1.4037x over previous
#include <cuda_runtime.h>
#include <cuda_bf16.h>
#include <cstdint>
#include <math.h>

#define BB 4
#define SS 4096
#define DD 1024
#define HH 64
#define NROW (BB*SS)

// Q scale: 1/8 softmax scale * log2(e) for ex2-based exp
#define QSC 0.18033688011112042f

// ---------------- scratch (__device__ globals; allocation-free rule) -------
__device__ uint32_t g_Qh[NROW*32], g_Ql[NROW*32];       // [row][d-pair] bf16x2
__device__ uint32_t g_Kh[NROW*32], g_Kl[NROW*32];       // [row][d-pair]
__device__ uint32_t g_Vth[BB*64*2048], g_Vtl[BB*64*2048]; // [b][h][seq-pair]
__device__ uint32_t g_Wth[192*512], g_Wtl[192*512];     // [n(=3*64)][d-pair]
__device__ float    g_O[2][NROW*64];                    // split-k partial O
__device__ float    g_L[2][NROW];                       // split-k partial rowsum

// ---------------- helpers --------------------------------------------------
__device__ __forceinline__ uint32_t smem_u32(const void* p){
    uint32_t a;
    asm("{ .reg .u64 t; cvta.to.shared.u64 t, %1; cvt.u32.u64 %0, t; }"
        : "=r"(a) : "l"(p));
    return a;
}
__device__ __forceinline__ void mma16816(float* d, const uint32_t* a,
                                         const uint32_t* b){
    asm volatile(
        "mma.sync.aligned.m16n8k16.row.col.f32.bf16.bf16.f32 "
        "{%0,%1,%2,%3}, {%4,%5,%6,%7}, {%8,%9}, {%0,%1,%2,%3};"
        : "+f"(d[0]), "+f"(d[1]), "+f"(d[2]), "+f"(d[3])
        : "r"(a[0]), "r"(a[1]), "r"(a[2]), "r"(a[3]), "r"(b[0]), "r"(b[1]));
}
__device__ __forceinline__ void ldsm4(uint32_t* r, uint32_t addr){
    asm volatile("ldmatrix.sync.aligned.m8n8.x4.shared.b16 {%0,%1,%2,%3}, [%4];"
        : "=r"(r[0]), "=r"(r[1]), "=r"(r[2]), "=r"(r[3]) : "r"(addr));
}
__device__ __forceinline__ void cpasync16(uint32_t dst, const void* src){
    asm volatile("cp.async.cg.shared.global [%0], [%1], 16;"
                 :: "r"(dst), "l"(src));
}
#define CP_COMMIT() asm volatile("cp.async.commit_group;" ::: "memory")
#define CP_WAIT1()  asm volatile("cp.async.wait_group 1;" ::: "memory")
#define CP_WAIT0()  asm volatile("cp.async.wait_group 0;" ::: "memory")

__device__ __forceinline__ float ex2(float x){
    float r; asm("ex2.approx.f32 %0, %1;" : "=f"(r) : "f"(x)); return r;
}
__device__ __forceinline__ uint32_t bfpack(float lo, float hi){
    uint32_t r;
    asm("cvt.rn.bf16x2.f32 %0, %1, %2;" : "=r"(r) : "f"(hi), "f"(lo));
    return r;
}
__device__ __forceinline__ void split2(float f0, float f1,
                                       uint32_t& hv, uint32_t& lv){
    hv = bfpack(f0, f1);
    float h0 = __uint_as_float(hv << 16);
    float h1 = __uint_as_float(hv & 0xffff0000u);
    lv = bfpack(f0 - h0, f1 - h1);
}
// swizzled byte offset inside a [row][128B] tile (conflict-free ldmatrix)
__device__ __forceinline__ uint32_t swz(int r, int bytecol){
    return (uint32_t)(r*128 + (bytecol ^ ((r & 7) << 4)));
}

// ---------------------------------------------------------------------------
// Kernel 0: transpose+split W -> g_Wth/g_Wtl [n][d-pair], n = reg*64+h
// ---------------------------------------------------------------------------
__global__ __launch_bounds__(256) void prep_w(
    const float* __restrict__ Wq, const float* __restrict__ Wk,
    const float* __restrict__ Wv)
{
    int idx = blockIdx.x*256 + threadIdx.x;
    if (idx >= 192*512) return;
    int n = idx >> 9, dp = idx & 511;
    const float* W = (n < 64) ? Wq : (n < 128) ? Wk : Wv;
    int h = n & 63, d = dp*2;
    uint32_t hv, lv;
    split2(W[d*64 + h], W[(d+1)*64 + h], hv, lv);
    g_Wth[idx] = hv;  g_Wtl[idx] = lv;
}

// ---------------------------------------------------------------------------
// Kernel 1: QKV via mma.sync.  128 CTAs x 256 thr.  CTA: 128 rows x 192 cols.
// smem: XH@0 XL@16384, WH@32768 WL@57344 = 80KB dynamic.
// ---------------------------------------------------------------------------
extern __shared__ char dsm[];

__global__ __launch_bounds__(256) void qkv_mma(const float* __restrict__ X)
{
    char* sm = dsm;
    uint32_t sb  = smem_u32(sm);
    const uint32_t xh = sb, xl = sb + 16384, wh = sb + 32768, wl = sb + 57344;

    const int tid = threadIdx.x, w = tid >> 5, lane = tid & 31;
    const int gid = lane >> 2, tig = lane & 3;
    const int row0 = blockIdx.x * 128;
    const int mrow = w * 16;

    const int aR   = mrow + (lane & 7) + ((lane >> 3) & 1) * 8;
    const uint32_t aOff = (uint32_t)aR * 128;
    const int aSeg = (lane >> 4) ? 16 : 0;
    const uint32_t aX = (uint32_t)((lane & 7) << 4);
    const uint32_t bOff = (uint32_t)((lane & 7) * 128);
    const int bSeg = (lane & 8) ? 16 : 0;
    const uint32_t bX = (uint32_t)((lane & 7) << 4);
    const int ntHi = (lane >> 4) & 1;

    float acc[24][4];
    #pragma unroll
    for (int nt = 0; nt < 24; ++nt)
        #pragma unroll
        for (int j = 0; j < 4; ++j) acc[nt][j] = 0.f;

    for (int kc = 0; kc < 16; ++kc) {
        const int d0 = kc * 64;
        #pragma unroll
        for (int i = 0; i < 16; ++i) {
            int idx = tid + 256*i;
            int r = idx >> 5, cp = idx & 31;
            float2 x = *(const float2*)(X + (size_t)(row0 + r)*DD + d0 + 2*cp);
            uint32_t hv, lv; split2(x.x, x.y, hv, lv);
            uint32_t off = swz(r, cp*4);
            *(uint32_t*)(sm + off)         = hv;
            *(uint32_t*)(sm + 16384 + off) = lv;
        }
        #pragma unroll
        for (int i = 0; i < 24; ++i) {
            int idx = tid + 256*i;
            int r = idx >> 5, cp = idx & 31;
            uint32_t src = (uint32_t)r*512 + (uint32_t)(d0 >> 1) + cp;
            uint32_t off = swz(r, cp*4);
            *(uint32_t*)(sm + 32768 + off) = g_Wth[src];
            *(uint32_t*)(sm + 57344 + off) = g_Wtl[src];
        }
        __syncthreads();

        #pragma unroll
        for (int ks = 0; ks < 4; ++ks) {
            uint32_t ah[4], al[4];
            uint32_t aoffs = aOff + (uint32_t)((ks*32 + aSeg) ^ aX);
            ldsm4(ah, xh + aoffs);
            ldsm4(al, xl + aoffs);
            uint32_t kk = bOff + (uint32_t)((ks*32 + bSeg) ^ bX);
            #pragma unroll
            for (int p = 0; p < 12; ++p) {
                uint32_t bh4[4], bl4[4];
                uint32_t ta = (uint32_t)((2*p + ntHi)*1024) + kk;
                ldsm4(bh4, wh + ta);
                ldsm4(bl4, wl + ta);
                mma16816(acc[2*p],   ah, bh4);
                mma16816(acc[2*p],   ah, bl4);
                mma16816(acc[2*p],   al, bh4);
                mma16816(acc[2*p+1], ah, bh4+2);
                mma16816(acc[2*p+1], ah, bl4+2);
                mma16816(acc[2*p+1], al, bh4+2);
            }
        }
        __syncthreads();
    }

    // epilogue: Q (x QSC) and K row-major split-bf16
    const int r0g = row0 + mrow + gid, r1g = r0g + 8;
    #pragma unroll
    for (int nt = 0; nt < 8; ++nt) {
        uint32_t hv, lv;
        split2(acc[nt][0]*QSC, acc[nt][1]*QSC, hv, lv);
        g_Qh[r0g*32 + nt*4 + tig] = hv;  g_Ql[r0g*32 + nt*4 + tig] = lv;
        split2(acc[nt][2]*QSC, acc[nt][3]*QSC, hv, lv);
        g_Qh[r1g*32 + nt*4 + tig] = hv;  g_Ql[r1g*32 + nt*4 + tig] = lv;
    }
    #pragma unroll
    for (int nt = 8; nt < 16; ++nt) {
        uint32_t hv, lv;
        int c = (nt - 8)*4 + tig;
        split2(acc[nt][0], acc[nt][1], hv, lv);
        g_Kh[r0g*32 + c] = hv;  g_Kl[r0g*32 + c] = lv;
        split2(acc[nt][2], acc[nt][3], hv, lv);
        g_Kh[r1g*32 + c] = hv;  g_Kl[r1g*32 + c] = lv;
    }
    // V: transpose through smem, split-write [b][h][seq-pair]
    __syncthreads();
    float* Vt = (float*)sm;
    #pragma unroll
    for (int nt = 16; nt < 24; ++nt) {
        int h0 = (nt - 16)*8 + tig*2;
        Vt[h0*128 + mrow + gid]         = acc[nt][0];
        Vt[(h0+1)*128 + mrow + gid]     = acc[nt][1];
        Vt[h0*128 + mrow + gid + 8]     = acc[nt][2];
        Vt[(h0+1)*128 + mrow + gid + 8] = acc[nt][3];
    }
    __syncthreads();
    const int bb = row0 >> 12, sloc = row0 & 4095;
    #pragma unroll
    for (int i = 0; i < 16; ++i) {
        int idx = tid + 256*i;
        int h = idx >> 6, sp = idx & 63;
        uint32_t hv, lv;
        split2(Vt[h*128 + 2*sp], Vt[h*128 + 2*sp + 1], hv, lv);
        size_t o = (size_t)(bb*64 + h)*2048 + (sloc >> 1) + sp;
        g_Vth[o] = hv;  g_Vtl[o] = lv;
    }
}

// ---------------------------------------------------------------------------
// Kernel 2: causal attention via mma.sync, split-bf16, no-max softmax.
// grid (32, 4): x = pair j (x>>1) + split s (x&1); y = batch.  128 CTAs.
// Each CTA runs TWO q-tiles (31-j then j) -> uniform ~33 k-tiles per CTA.
// cp.async double-buffered K/V staging (2 x 32KB dynamic smem).
// ---------------------------------------------------------------------------
__global__ __launch_bounds__(256) void attn_mma()
{
    char* sm = dsm;
    uint32_t sb = smem_u32(sm);
    const int tid = threadIdx.x, w = tid >> 5, lane = tid & 31;
    const int gid = lane >> 2, tig = lane & 3;
    const int j = blockIdx.x >> 1;
    const int s = blockIdx.x & 1;
    const int b = blockIdx.y;

    const uint32_t bOff = (uint32_t)((lane & 7) * 128);
    const int bSeg = (lane & 8) ? 16 : 0;
    const uint32_t bX = (uint32_t)((lane & 7) << 4);
    const int ntHi = (lane >> 4) & 1;

    const uint32_t* KH = g_Kh + (size_t)(b*SS)*32;
    const uint32_t* KL = g_Kl + (size_t)(b*SS)*32;
    const uint32_t* VH = g_Vth + (size_t)(b*64)*2048;
    const uint32_t* VL = g_Vtl + (size_t)(b*64)*2048;

    for (int phase = 0; phase < 2; ++phase) {
        const int qq = phase ? j : (31 - j);
        const int q0 = qq * 128;
        const int n  = qq + 1;                     // k-tiles: kt = s + 2t

        // Q fragments (registers)
        const int r0g = b*SS + q0 + w*16 + gid, r1g = r0g + 8;
        uint32_t qfh[4][4], qfl[4][4];
        #pragma unroll
        for (int ks = 0; ks < 4; ++ks) {
            qfh[ks][0] = g_Qh[r0g*32 + ks*8 + tig];
            qfh[ks][1] = g_Qh[r1g*32 + ks*8 + tig];
            qfh[ks][2] = g_Qh[r0g*32 + ks*8 + 4 + tig];
            qfh[ks][3] = g_Qh[r1g*32 + ks*8 + 4 + tig];
            qfl[ks][0] = g_Ql[r0g*32 + ks*8 + tig];
            qfl[ks][1] = g_Ql[r1g*32 + ks*8 + tig];
            qfl[ks][2] = g_Ql[r0g*32 + ks*8 + 4 + tig];
            qfl[ks][3] = g_Ql[r1g*32 + ks*8 + 4 + tig];
        }

        float oc[8][4];
        #pragma unroll
        for (int nt = 0; nt < 8; ++nt)
            #pragma unroll
            for (int c = 0; c < 4; ++c) oc[nt][c] = 0.f;
        float ls0 = 0.f, ls1 = 0.f;
        const int qg0 = q0 + w*16 + gid, qg1 = qg0 + 8;

        // stage issuer: buf in {0,1}, tile start k0
        #define STAGE(buf, k0) do {                                           \
            uint32_t _b = sb + (uint32_t)(buf)*32768;                         \
            _Pragma("unroll")                                                 \
            for (int _i = 0; _i < 2; ++_i) {                                  \
                int _idx = tid + 256*_i;                                      \
                int _r = _idx >> 3, _c4 = _idx & 7;                           \
                uint32_t _o = swz(_r, _c4*16);                                \
                cpasync16(_b + _o,         KH + (size_t)((k0)+_r)*32 + _c4*4);\
                cpasync16(_b + 8192 + _o,  KL + (size_t)((k0)+_r)*32 + _c4*4);\
                cpasync16(_b + 16384 + _o, VH + (size_t)_r*2048 + ((k0)>>1) + _c4*4);\
                cpasync16(_b + 24576 + _o, VL + (size_t)_r*2048 + ((k0)>>1) + _c4*4);\
            }                                                                 \
            CP_COMMIT();                                                      \
        } while (0)

        STAGE(0, s*64);

        for (int t = 0; t < n; ++t) {
            const int k0 = (s + 2*t) * 64;
            const bool more = (t + 1 < n);
            if (more) STAGE((t+1) & 1, (s + 2*(t+1))*64);
            if (more) CP_WAIT1(); else CP_WAIT0();
            __syncthreads();
            const uint32_t st = sb + (uint32_t)((t & 1) * 32768);

            // scores
            float sc[8][4];
            #pragma unroll
            for (int nt = 0; nt < 8; ++nt)
                #pragma unroll
                for (int c = 0; c < 4; ++c) sc[nt][c] = 0.f;
            #pragma unroll
            for (int ks = 0; ks < 4; ++ks) {
                uint32_t kk = bOff + (uint32_t)((ks*32 + bSeg) ^ bX);
                #pragma unroll
                for (int p = 0; p < 4; ++p) {
                    uint32_t bh4[4], bl4[4];
                    uint32_t ta = st + (uint32_t)((2*p + ntHi)*1024) + kk;
                    ldsm4(bh4, ta);
                    ldsm4(bl4, ta + 8192);
                    mma16816(sc[2*p],   qfh[ks], bh4);
                    mma16816(sc[2*p],   qfh[ks], bl4);
                    mma16816(sc[2*p],   qfl[ks], bh4);
                    mma16816(sc[2*p+1], qfh[ks], bh4+2);
                    mma16816(sc[2*p+1], qfh[ks], bl4+2);
                    mma16816(sc[2*p+1], qfl[ks], bh4+2);
                }
            }

            // mask + exp2 + split P into A-fragment layout (registers only)
            uint32_t ph[16], pl[16];
            #pragma unroll
            for (int nt = 0; nt < 8; ++nt) {
                int kg = k0 + nt*8 + tig*2;
                float p0 = (kg     <= qg0) ? ex2(sc[nt][0]) : 0.f;
                float p1 = (kg + 1 <= qg0) ? ex2(sc[nt][1]) : 0.f;
                float p2 = (kg     <= qg1) ? ex2(sc[nt][2]) : 0.f;
                float p3 = (kg + 1 <= qg1) ? ex2(sc[nt][3]) : 0.f;
                ls0 += p0 + p1;  ls1 += p2 + p3;
                split2(p0, p1, ph[nt*2],     pl[nt*2]);
                split2(p2, p3, ph[nt*2 + 1], pl[nt*2 + 1]);
            }

            // O += P . Vt^T
            #pragma unroll
            for (int kc = 0; kc < 4; ++kc) {
                uint32_t kk = bOff + (uint32_t)((kc*32 + bSeg) ^ bX);
                const uint32_t* ahp = &ph[kc*4];
                const uint32_t* alp = &pl[kc*4];
                #pragma unroll
                for (int p = 0; p < 4; ++p) {
                    uint32_t bh4[4], bl4[4];
                    uint32_t ta = st + 16384 + (uint32_t)((2*p + ntHi)*1024) + kk;
                    ldsm4(bh4, ta);
                    ldsm4(bl4, ta + 8192);
                    mma16816(oc[2*p],   ahp, bh4);
                    mma16816(oc[2*p],   ahp, bl4);
                    mma16816(oc[2*p],   alp, bh4);
                    mma16816(oc[2*p+1], ahp, bh4+2);
                    mma16816(oc[2*p+1], ahp, bl4+2);
                    mma16816(oc[2*p+1], alp, bh4+2);
                }
            }
            __syncthreads();
        }
        #undef STAGE

        // write partial O + partial row sums
        float* Og = g_O[s];
        const size_t ob0 = (size_t)(b*SS + q0 + w*16 + gid)*64;
        #pragma unroll
        for (int nt = 0; nt < 8; ++nt) {
            *(float2*)&Og[ob0 + nt*8 + tig*2]        = make_float2(oc[nt][0], oc[nt][1]);
            *(float2*)&Og[ob0 + 8*64 + nt*8 + tig*2] = make_float2(oc[nt][2], oc[nt][3]);
        }
        ls0 += __shfl_xor_sync(0xffffffffu, ls0, 1);
        ls0 += __shfl_xor_sync(0xffffffffu, ls0, 2);
        ls1 += __shfl_xor_sync(0xffffffffu, ls1, 1);
        ls1 += __shfl_xor_sync(0xffffffffu, ls1, 2);
        if (tig == 0) {
            g_L[s][b*SS + q0 + w*16 + gid]     = ls0;
            g_L[s][b*SS + q0 + w*16 + gid + 8] = ls1;
        }
    }
}

// ---------------------------------------------------------------------------
// Kernel 3: combine split-k partials and normalize (float4).
// ---------------------------------------------------------------------------
__global__ __launch_bounds__(256) void finalize(float* __restrict__ out)
{
    int idx = blockIdx.x*256 + threadIdx.x;        // over NROW*16 float4s
    float4 a = ((const float4*)g_O[0])[idx];
    float4 c = ((const float4*)g_O[1])[idx];
    int row = idx >> 4;
    float linv = 1.f / (g_L[0][row] + g_L[1][row]);
    float4 r;
    r.x = (a.x + c.x) * linv;
    r.y = (a.y + c.y) * linv;
    r.z = (a.z + c.z) * linv;
    r.w = (a.w + c.w) * linv;
    ((float4*)out)[idx] = r;
}

// ---------------------------------------------------------------------------
extern "C" void kernel_launch(void* const* d_in, const int* in_sizes, int n_in,
                              void* d_out, int out_size)
{
    const float* X  = (const float*)d_in[0];
    const float* Wq = (const float*)d_in[1];
    const float* Wk = (const float*)d_in[2];
    const float* Wv = (const float*)d_in[3];
    float* out = (float*)d_out;

    prep_w<<<384, 256>>>(Wq, Wk, Wv);

    const int qkv_smem = 81920;
    cudaFuncSetAttribute(qkv_mma,
                         cudaFuncAttributeMaxDynamicSharedMemorySize, qkv_smem);
    qkv_mma<<<128, 256, qkv_smem>>>(X);

    const int attn_smem = 65536;
    cudaFuncSetAttribute(attn_mma,
                         cudaFuncAttributeMaxDynamicSharedMemorySize, attn_smem);
    attn_mma<<<dim3(32, BB), 256, attn_smem>>>();

    finalize<<<(NROW*16)/256, 256>>>(out);
}